// round 1
// baseline (speedup 1.0000x reference)
#include <cuda_runtime.h>

// 4-qubit statevector simulation, one thread per patch.
// State index i: bit3 (value 8) = qubit 0 ... bit0 (value 1) = qubit 3
// (matches jnp reshape (N,2,2,2,2) with axis 1+q = qubit q).

__global__ __launch_bounds__(256) void quanv_kernel(
    const float* __restrict__ x,      // [n, 4] angles in [0,1)
    const float* __restrict__ params, // [7]
    float* __restrict__ out,          // [n, 4] expectations
    int n)
{
    int idx = blockIdx.x * blockDim.x + threadIdx.x;
    if (idx >= n) return;

    float4 a = ((const float4*)x)[idx];

    // ---- param half-angle sin/cos (broadcast loads, hit L2/const path) ----
    float cp[7], sp[7];
    #pragma unroll
    for (int i = 0; i < 7; i++) {
        sincosf(0.5f * __ldg(params + i), &sp[i], &cp[i]);
    }

    // ---- encoding: RY(pi * x_q)|0> per qubit -> real product state ----
    float cs[4], sn[4];
    sincospif(0.5f * a.x, &sn[0], &cs[0]);
    sincospif(0.5f * a.y, &sn[1], &cs[1]);
    sincospif(0.5f * a.z, &sn[2], &cs[2]);
    sincospif(0.5f * a.w, &sn[3], &cs[3]);

    float re[16], im[16];
    #pragma unroll
    for (int i = 0; i < 16; i++) {
        float v = ((i & 8) ? sn[0] : cs[0])
                * ((i & 4) ? sn[1] : cs[1])
                * ((i & 2) ? sn[2] : cs[2])
                * ((i & 1) ? sn[3] : cs[3]);
        re[i] = v;
        im[i] = 0.0f;
    }

    // ---- layer 1: RX(p0) q0, RY(p1) q1, RZ(p2) q2, H q3 ----

    // RX(p0) on q0 (mask 8): [[c, -i s], [-i s, c]]
    {
        float cc = cp[0], ss = sp[0];
        #pragma unroll
        for (int i = 0; i < 16; i++) {
            if (!(i & 8)) {
                int j = i | 8;
                float r0 = re[i], i0 = im[i], r1 = re[j], i1 = im[j];
                re[i] =  cc * r0 + ss * i1;
                im[i] =  cc * i0 - ss * r1;
                re[j] =  ss * i0 + cc * r1;
                im[j] = -ss * r0 + cc * i1;
            }
        }
    }

    // RY(p1) on q1 (mask 4): [[c, -s], [s, c]] (real)
    {
        float cc = cp[1], ss = sp[1];
        #pragma unroll
        for (int i = 0; i < 16; i++) {
            if (!(i & 4)) {
                int j = i | 4;
                float r0 = re[i], i0 = im[i], r1 = re[j], i1 = im[j];
                re[i] = cc * r0 - ss * r1;
                im[i] = cc * i0 - ss * i1;
                re[j] = ss * r0 + cc * r1;
                im[j] = ss * i0 + cc * i1;
            }
        }
    }

    // RZ(p2) on q2 (mask 2): diag(c - i s, c + i s)
    {
        float cc = cp[2], ss = sp[2];
        #pragma unroll
        for (int i = 0; i < 16; i++) {
            if (!(i & 2)) {
                int j = i | 2;
                float r0 = re[i], i0 = im[i], r1 = re[j], i1 = im[j];
                re[i] = cc * r0 + ss * i0;
                im[i] = cc * i0 - ss * r0;
                re[j] = cc * r1 - ss * i1;
                im[j] = cc * i1 + ss * r1;
            }
        }
    }

    // H on q3 (mask 1)
    {
        const float inv = 0.70710678118654752440f;
        #pragma unroll
        for (int i = 0; i < 16; i++) {
            if (!(i & 1)) {
                int j = i | 1;
                float r0 = re[i], i0 = im[i], r1 = re[j], i1 = im[j];
                re[i] = (r0 + r1) * inv;
                im[i] = (i0 + i1) * inv;
                re[j] = (r0 - r1) * inv;
                im[j] = (i0 - i1) * inv;
            }
        }
    }

    // ---- layer 2: CNOT(0,1), CNOT(1,2), CNOT(2,3), CNOT(3,0) ----
    // CNOT(c,t): for states with control bit set, swap target-bit pair.
    #pragma unroll
    for (int g = 0; g < 4; g++) {
        const int cm = (g == 0) ? 8 : (g == 1) ? 4 : (g == 2) ? 2 : 1;
        const int tm = (g == 0) ? 4 : (g == 1) ? 2 : (g == 2) ? 1 : 8;
        #pragma unroll
        for (int i = 0; i < 16; i++) {
            if ((i & cm) && !(i & tm)) {
                int j = i | tm;
                float tr = re[i]; re[i] = re[j]; re[j] = tr;
                float ti = im[i]; im[i] = im[j]; im[j] = ti;
            }
        }
    }

    // ---- layer 3: RY(p3..p6) on q0..q3 ----
    #pragma unroll
    for (int q = 0; q < 4; q++) {
        const int m = 8 >> q;
        float cc = cp[3 + q], ss = sp[3 + q];
        #pragma unroll
        for (int i = 0; i < 16; i++) {
            if (!(i & m)) {
                int j = i | m;
                float r0 = re[i], i0 = im[i], r1 = re[j], i1 = im[j];
                re[i] = cc * r0 - ss * r1;
                im[i] = cc * i0 - ss * i1;
                re[j] = ss * r0 + cc * r1;
                im[j] = ss * i0 + cc * i1;
            }
        }
    }

    // ---- expectations <Z_q> = sum_{bit q = 0} p - sum_{bit q = 1} p ----
    float z0 = 0.f, z1 = 0.f, z2 = 0.f, z3 = 0.f;
    #pragma unroll
    for (int i = 0; i < 16; i++) {
        float p = re[i] * re[i] + im[i] * im[i];
        z0 += (i & 8) ? -p : p;
        z1 += (i & 4) ? -p : p;
        z2 += (i & 2) ? -p : p;
        z3 += (i & 1) ? -p : p;
    }

    float4 o;
    o.x = z0; o.y = z1; o.z = z2; o.w = z3;
    ((float4*)out)[idx] = o;
}

extern "C" void kernel_launch(void* const* d_in, const int* in_sizes, int n_in,
                              void* d_out, int out_size)
{
    const float* x      = (const float*)d_in[0];   // [2048,3,196,4] fp32
    const float* params = (const float*)d_in[1];   // [7] fp32
    float* out = (float*)d_out;                    // [2048,28,28,3] fp32 (contiguous view of [n,4])

    int n = in_sizes[0] / 4;                       // patches
    int threads = 256;
    int blocks = (n + threads - 1) / threads;
    quanv_kernel<<<blocks, threads>>>(x, params, out, n);
}

// round 2
// speedup vs baseline: 2.7732x; 2.7732x over previous
#include <cuda_runtime.h>

// Quanv layer, fully collapsed:
//   out_q = cos(p_{3+q}) * <Z_q>_w  -  sin(p_{3+q}) * <X_q>_w
// where w = state after encoding + layer1 + CNOT ring. Pulling the Paulis
// back through the CNOTs gives pure X/Z strings over the (product) state
// after layer1, so everything factorizes into per-qubit Bloch components.

__device__ float g_const[11];
// [0] = cos(p0)          (RX on q0)
// [1] = p1 / pi          (RY on q1, folded into sincospi argument)
// [2] = cos(p2)          (RZ on q2)
// [3..6]  = cos(p3..p6)  (layer-3 RY)
// [7..10] = sin(p3..p6)

__global__ void setup_kernel(const float* __restrict__ params)
{
    const float inv_pi = 0.31830988618379067154f;
    g_const[0] = cosf(params[0]);
    g_const[1] = params[1] * inv_pi;
    g_const[2] = cosf(params[2]);
    #pragma unroll
    for (int q = 0; q < 4; q++) {
        float s, c;
        sincosf(params[3 + q], &s, &c);
        g_const[3 + q] = c;
        g_const[7 + q] = s;
    }
}

__global__ __launch_bounds__(256) void quanv_kernel(
    const float* __restrict__ x,   // [n, 4] angles in [0,1)
    float* __restrict__ out,       // [n, 4]
    int n)
{
    int idx = blockIdx.x * blockDim.x + threadIdx.x;
    if (idx >= n) return;

    float4 a = ((const float4*)x)[idx];

    float Cp0   = __ldg(&g_const[0]);
    float p1opi = __ldg(&g_const[1]);
    float Cp2   = __ldg(&g_const[2]);
    float C3 = __ldg(&g_const[3]), C4 = __ldg(&g_const[4]);
    float C5 = __ldg(&g_const[5]), C6 = __ldg(&g_const[6]);
    float S3 = __ldg(&g_const[7]), S4 = __ldg(&g_const[8]);
    float S5 = __ldg(&g_const[9]), S6 = __ldg(&g_const[10]);

    // Per-qubit Bloch (x, z) after encoding RY(pi*a_q) and layer-1 gate.
    float s0, c0; sincospif(a.x, &s0, &c0);          // enc q0
    float x0 = s0;                                    // RX leaves X
    float z0 = Cp0 * c0;                              // RX: z' = cos(p0)*z (y=0)

    float s1, c1; sincospif(a.y + p1opi, &s1, &c1);   // RY(p1) adds angles
    float x1 = s1;
    float z1 = c1;

    float s2, c2; sincospif(a.z, &s2, &c2);           // enc q2
    float x2 = Cp2 * s2;                              // RZ: x' = cos(p2)*x
    float z2 = c2;                                    // RZ leaves Z

    float s3, c3; sincospif(a.w, &s3, &c3);           // enc q3
    float x3 = c3;                                    // H: X <-> Z
    float z3 = s3;

    // Pauli strings after conjugating Z_q / X_q through the CNOT ring.
    float z01 = z0 * z1;
    float z23 = z2 * z3;
    float Z0w = z1 * z23;        // Z1 Z2 Z3
    float Z1w = z01;             // Z0 Z1
    float Z2w = z01 * z2;        // Z0 Z1 Z2
    float Z3w = z01 * z23;       // Z0 Z1 Z2 Z3

    float x01 = x0 * x1;
    float X0w = x01;             // X0 X1
    float X1w = x1 * x2;         // X1 X2
    float X2w = x2 * x3;         // X2 X3
    float X3w = x01 * x3;        // X0 X1 X3

    float4 o;
    o.x = fmaf(C3, Z0w, -S3 * X0w);
    o.y = fmaf(C4, Z1w, -S4 * X1w);
    o.z = fmaf(C5, Z2w, -S5 * X2w);
    o.w = fmaf(C6, Z3w, -S6 * X3w);
    ((float4*)out)[idx] = o;
}

extern "C" void kernel_launch(void* const* d_in, const int* in_sizes, int n_in,
                              void* d_out, int out_size)
{
    const float* x      = (const float*)d_in[0];   // [2048,3,196,4] fp32
    const float* params = (const float*)d_in[1];   // [7] fp32
    float* out = (float*)d_out;                    // [2048,28,28,3] fp32 (flat [n,4])

    setup_kernel<<<1, 1>>>(params);

    int n = in_sizes[0] / 4;
    int threads = 256;
    int blocks = (n + threads - 1) / threads;
    quanv_kernel<<<blocks, threads>>>(x, out, n);
}

// round 3
// speedup vs baseline: 3.3940x; 1.2239x over previous
#include <cuda_runtime.h>

// Quanv layer, circuit collapsed to per-qubit Bloch components + Pauli strings:
//   out_q = cos(p_{3+q}) * <Z_q>_w  -  sin(p_{3+q}) * <X_q>_w
// Fast MUFU trig (args in [0, pi+p], abs err ~5e-7, tolerance 1e-3).

__device__ float4 g_c[3];
// g_c[0] = (cos p0, p1, cos p2, 0)
// g_c[1] = (cos p3, cos p4, cos p5, cos p6)
// g_c[2] = (sin p3, sin p4, sin p5, sin p6)

__global__ void setup_kernel(const float* __restrict__ params)
{
    float4 c0, c1, c2;
    c0.x = cosf(params[0]);
    c0.y = params[1];
    c0.z = cosf(params[2]);
    c0.w = 0.0f;
    float s, c;
    sincosf(params[3], &s, &c); c1.x = c; c2.x = s;
    sincosf(params[4], &s, &c); c1.y = c; c2.y = s;
    sincosf(params[5], &s, &c); c1.z = c; c2.z = s;
    sincosf(params[6], &s, &c); c1.w = c; c2.w = s;
    g_c[0] = c0; g_c[1] = c1; g_c[2] = c2;
}

__device__ __forceinline__ float4 quanv_one(
    float4 a, float Cp0, float p1, float Cp2,
    float4 C, float4 S)
{
    const float PI = 3.14159265358979323846f;

    // Per-qubit Bloch (x, z) after encoding RY(pi*a_q) + layer-1 gate.
    float t0 = a.x * PI;
    float x0 = __sinf(t0);              // RX leaves X
    float z0 = Cp0 * __cosf(t0);        // RX: z' = cos(p0) * z   (y = 0)

    float t1 = fmaf(a.y, PI, p1);       // RY(p1) adds angles
    float x1 = __sinf(t1);
    float z1 = __cosf(t1);

    float t2 = a.z * PI;
    float x2 = Cp2 * __sinf(t2);        // RZ: x' = cos(p2) * x
    float z2 = __cosf(t2);              // RZ leaves Z

    float t3 = a.w * PI;
    float x3 = __cosf(t3);              // H swaps X <-> Z
    float z3 = __sinf(t3);

    // Pauli strings after conjugating Z_q / X_q through the CNOT ring.
    float z01 = z0 * z1;
    float z23 = z2 * z3;
    float Z0w = z1 * z23;               // Z1 Z2 Z3
    float Z1w = z01;                    // Z0 Z1
    float Z2w = z01 * z2;               // Z0 Z1 Z2
    float Z3w = z01 * z23;              // Z0 Z1 Z2 Z3

    float x01 = x0 * x1;
    float X0w = x01;                    // X0 X1
    float X1w = x1 * x2;                // X1 X2
    float X2w = x2 * x3;                // X2 X3
    float X3w = x01 * x3;               // X0 X1 X3

    float4 o;
    o.x = fmaf(C.x, Z0w, -S.x * X0w);
    o.y = fmaf(C.y, Z1w, -S.y * X1w);
    o.z = fmaf(C.z, Z2w, -S.z * X2w);
    o.w = fmaf(C.w, Z3w, -S.w * X3w);
    return o;
}

__global__ __launch_bounds__(256) void quanv_kernel(
    const float* __restrict__ x,   // [n, 4] angles
    float* __restrict__ out,       // [n, 4]
    int n)
{
    int half = n >> 1;
    int idx = blockIdx.x * blockDim.x + threadIdx.x;
    if (idx >= half) return;

    const float4* xin = (const float4*)x;
    float4* xout = (float4*)out;

    // Two coalesced streams: [0, half) and [half, n).
    float4 a0 = xin[idx];
    float4 a1 = xin[idx + half];

    float4 c0 = g_c[0];
    float4 C  = g_c[1];
    float4 S  = g_c[2];

    float4 o0 = quanv_one(a0, c0.x, c0.y, c0.z, C, S);
    float4 o1 = quanv_one(a1, c0.x, c0.y, c0.z, C, S);

    xout[idx] = o0;
    xout[idx + half] = o1;

    // Tail (n odd — not hit for this problem's shapes, kept for safety).
    if (idx == 0 && (n & 1)) {
        float4 at = xin[n - 1];
        xout[n - 1] = quanv_one(at, c0.x, c0.y, c0.z, C, S);
    }
}

extern "C" void kernel_launch(void* const* d_in, const int* in_sizes, int n_in,
                              void* d_out, int out_size)
{
    const float* x      = (const float*)d_in[0];   // [2048,3,196,4] fp32
    const float* params = (const float*)d_in[1];   // [7] fp32
    float* out = (float*)d_out;                    // flat [n,4] fp32

    setup_kernel<<<1, 1>>>(params);

    int n = in_sizes[0] / 4;       // patches
    int half = n >> 1;
    int threads = 256;
    int blocks = (half + threads - 1) / threads;
    quanv_kernel<<<blocks, threads>>>(x, out, n);
}